// round 4
// baseline (speedup 1.0000x reference)
#include <cuda_runtime.h>

#define NN 8192
#define INDIM 512
#define HID 50
#define ZD 128
#define NCAT 64
#define EPSV 1e-8f
#define NWORK_MAX (NN/32 + NCAT)

// ---------------- scratch (device globals; no allocation allowed) ----------
__device__ float g_fx[NN*ZD];
__device__ float g_fz[NN*ZD];
__device__ float g_u [NN*ZD];
__device__ float g_T [NN];
__device__ int   g_cnt[NCAT], g_start[NCAT];
__device__ int   g_sorted[NN];
__device__ int   g_work[NWORK_MAX];
__device__ int   g_nwork;

__device__ __forceinline__ float softplusf(float v){
    // stable: log1p(exp(v)) = max(v,0) + log1p(exp(-|v|))
    return fmaxf(v, 0.f) + log1pf(expf(-fabsf(v)));
}

// ---------------- fused bucket sort (single block) --------------------------
// histogram -> scan -> worklist -> scatter, all in one 1024-thread block.
__global__ void bucket_kernel(const int* __restrict__ c){
    __shared__ int s_cnt[NCAT];
    __shared__ int s_start[NCAT];
    __shared__ int s_cursor[NCAT];
    __shared__ int s_cat[NN];
    int tid = threadIdx.x;

    if (tid < NCAT) s_cnt[tid] = 0;
    __syncthreads();

    for (int i = tid; i < NN; i += 1024){
        int cc = c[i];
        cc = min(max(cc, 0), NCAT - 1);     // defensive clamp
        s_cat[i] = cc;
        atomicAdd(&s_cnt[cc], 1);
    }
    __syncthreads();

    if (tid == 0){
        int s = 0, w = 0;
        for (int cc = 0; cc < NCAT; cc++){
            s_start[cc]  = s;
            s_cursor[cc] = s;
            g_start[cc]  = s;
            int n = s_cnt[cc];
            g_cnt[cc] = n;
            s += n;
            int nt = (n + 31) >> 5;
            for (int t = 0; t < nt; t++) g_work[w++] = (cc << 16) | t;
        }
        g_nwork = w;
    }
    __syncthreads();

    for (int i = tid; i < NN; i += 1024){
        int p = atomicAdd(&s_cursor[s_cat[i]], 1);
        g_sorted[p] = i;
    }
}

// ---------------- fx = relu(x@W1+b1)@W2+b2  (64 rows / block) --------------
__global__ void fx_kernel(const float* __restrict__ x,  const float* __restrict__ W1,
                          const float* __restrict__ b1, const float* __restrict__ W2,
                          const float* __restrict__ b2){
    __shared__ float sbuf[9664];          // reuse: GEMM1 tiles, then Hs + W2s
    __shared__ float b1s[64];
    __shared__ float b2s[128];
    float (*As)[33]   = (float(*)[33])  sbuf;               // 64x33  (2112)
    float (*Bs)[64]   = (float(*)[64])  (sbuf + 2112);      // 32x64  (2048)
    float (*Hs)[51]   = (float(*)[51])  sbuf;               // 64x51  (3264)  overlaps As/Bs (dead)
    float (*W2s)[128] = (float(*)[128]) (sbuf + 3264);      // 50x128 (6400)

    int tid  = threadIdx.x;
    int row0 = blockIdx.x * 64;
    if (tid < 64)  b1s[tid] = (tid < HID) ? b1[tid] : 0.f;
    if (tid < 128) b2s[tid] = b2[tid];

    int rg = (tid >> 4) * 4;     // 0..60
    int cg = (tid & 15) * 4;     // 0..60
    float acc[4][4] = {};

    for (int k0 = 0; k0 < INDIM; k0 += 32){
        for (int e = tid; e < 64*32; e += 256){
            int r = e >> 5, k = e & 31;
            As[r][k] = x[(row0 + r)*INDIM + k0 + k];
        }
        for (int e = tid; e < 32*64; e += 256){
            int k = e >> 6, j = e & 63;
            Bs[k][j] = (j < HID) ? W1[(k0 + k)*HID + j] : 0.f;
        }
        __syncthreads();
        #pragma unroll
        for (int k = 0; k < 32; k++){
            float a[4], b[4];
            #pragma unroll
            for (int i = 0; i < 4; i++) a[i] = As[rg+i][k];
            #pragma unroll
            for (int j = 0; j < 4; j++) b[j] = Bs[k][cg+j];
            #pragma unroll
            for (int i = 0; i < 4; i++)
                #pragma unroll
                for (int j = 0; j < 4; j++) acc[i][j] += a[i]*b[j];
        }
        __syncthreads();
    }

    // write hidden (ReLU) and stage W2 (regions disjoint; As/Bs dead)
    #pragma unroll
    for (int i = 0; i < 4; i++)
        #pragma unroll
        for (int j = 0; j < 4; j++){
            int cc = cg + j;
            if (cc < HID) Hs[rg+i][cc] = fmaxf(acc[i][j] + b1s[cc], 0.f);
        }
    for (int e = tid; e < HID*128; e += 256) W2s[e >> 7][e & 127] = W2[e];
    __syncthreads();

    for (int e = tid; e < 64*128; e += 256){
        int r = e >> 7, cc = e & 127;
        float v = b2s[cc];
        #pragma unroll
        for (int k = 0; k < HID; k++) v += Hs[r][k]*W2s[k][cc];
        g_fx[(row0 + r)*ZD + cc] = v;
    }
}

// ---------------- fz = z@Wz+bz  (64 rows / block, k-tiled) -----------------
__global__ void fz_kernel(const float* __restrict__ z, const float* __restrict__ Wz,
                          const float* __restrict__ bz){
    __shared__ float Zs[64][33];
    __shared__ float Wzt[32][128];
    __shared__ float bzs[128];
    int tid  = threadIdx.x;
    int row0 = blockIdx.x * 64;
    if (tid < 128) bzs[tid] = bz[tid];

    int rg = (tid >> 4) * 4;     // 0..60
    int cg = (tid & 15) * 8;     // 0..120
    float acc[4][8] = {};

    for (int kt = 0; kt < ZD; kt += 32){
        for (int e = tid; e < 64*32; e += 256){
            int r = e >> 5, k = e & 31;
            Zs[r][k] = z[(row0 + r)*ZD + kt + k];
        }
        for (int e = tid; e < 32*128; e += 256){
            int k = e >> 7, cc = e & 127;
            Wzt[k][cc] = Wz[(kt + k)*ZD + cc];
        }
        __syncthreads();
        #pragma unroll
        for (int k = 0; k < 32; k++){
            float a[4], b[8];
            #pragma unroll
            for (int i = 0; i < 4; i++) a[i] = Zs[rg+i][k];
            #pragma unroll
            for (int j = 0; j < 8; j++) b[j] = Wzt[k][cg+j];
            #pragma unroll
            for (int i = 0; i < 4; i++)
                #pragma unroll
                for (int j = 0; j < 8; j++) acc[i][j] += a[i]*b[j];
        }
        __syncthreads();
    }
    #pragma unroll
    for (int i = 0; i < 4; i++)
        #pragma unroll
        for (int j = 0; j < 8; j++)
            g_fz[(row0 + rg + i)*ZD + cg + j] = acc[i][j] + bzs[cg+j];
}

// ---------------- u = fx @ Ws[cat]; T = softplus(u . fz) -------------------
// block = one (cat, 32-row tile) work item
__global__ void u_kernel(const float* __restrict__ Ws){
    __shared__ float Fxs[32][129];
    __shared__ float Wst[32][128];
    __shared__ int   gidx[32];
    int w = blockIdx.x;
    if (w >= g_nwork) return;
    int item  = g_work[w];
    int cat   = item >> 16, tile = item & 0xffff;
    int start = g_start[cat], cnt = g_cnt[cat];
    int i0    = tile * 32;
    int ni    = min(32, cnt - i0);
    int tid   = threadIdx.x;

    if (tid < 32) gidx[tid] = (tid < ni) ? g_sorted[start + i0 + tid] : 0;
    __syncthreads();
    for (int e = tid; e < 32*ZD; e += 256){
        int r = e >> 7, k = e & 127;
        Fxs[r][k] = (r < ni) ? g_fx[gidx[r]*ZD + k] : 0.f;
    }

    const float* Wc = Ws + (size_t)cat*ZD*ZD;
    int r0 = (tid >> 5) * 4;     // warp-uniform
    int c0 = (tid & 31) * 4;
    float acc[4][4] = {};

    for (int kt = 0; kt < ZD; kt += 32){
        __syncthreads();                       // Fxs visible / Wst reuse safe
        for (int e = tid; e < 32*128; e += 256){
            int k = e >> 7, cc = e & 127;
            Wst[k][cc] = Wc[(kt + k)*ZD + cc];
        }
        __syncthreads();
        #pragma unroll
        for (int k = 0; k < 32; k++){
            float a[4], b[4];
            #pragma unroll
            for (int i = 0; i < 4; i++) a[i] = Fxs[r0+i][kt+k];
            #pragma unroll
            for (int j = 0; j < 4; j++) b[j] = Wst[k][c0+j];
            #pragma unroll
            for (int i = 0; i < 4; i++)
                #pragma unroll
                for (int j = 0; j < 4; j++) acc[i][j] += a[i]*b[j];
        }
    }

    int lane = tid & 31;
    #pragma unroll
    for (int i = 0; i < 4; i++){
        int rr = r0 + i;                       // warp-uniform
        int gi = (rr < ni) ? gidx[rr] : 0;
        if (rr < ni){
            float4 v = make_float4(acc[i][0], acc[i][1], acc[i][2], acc[i][3]);
            *(float4*)&g_u[(size_t)gi*ZD + c0] = v;
        }
        float p = 0.f;
        if (rr < ni){
            const float4 fzr = *(const float4*)&g_fz[(size_t)gi*ZD + c0];
            p = acc[i][0]*fzr.x + acc[i][1]*fzr.y + acc[i][2]*fzr.z + acc[i][3]*fzr.w;
        }
        p += __shfl_xor_sync(0xffffffffu, p, 16);
        p += __shfl_xor_sync(0xffffffffu, p, 8);
        p += __shfl_xor_sync(0xffffffffu, p, 4);
        p += __shfl_xor_sync(0xffffffffu, p, 2);
        p += __shfl_xor_sync(0xffffffffu, p, 1);
        if (lane == 0 && rr < ni) g_T[gi] = softplusf(p);
    }
}

// ---------------- neg_T + final output -------------------------------------
// block = one (cat, 32-row tile); loops over all fz rows of the same category
__global__ void neg_kernel(float* __restrict__ out){
    __shared__ float Us[32][129];
    __shared__ float Fs[32][129];
    __shared__ int   gidx[32];
    __shared__ int   jidx[32];
    int w = blockIdx.x;
    if (w >= g_nwork) return;
    int item  = g_work[w];
    int cat   = item >> 16, tile = item & 0xffff;
    int start = g_start[cat], cnt = g_cnt[cat];
    int i0    = tile * 32;
    int ni    = min(32, cnt - i0);
    int tid   = threadIdx.x;

    if (tid < 32) gidx[tid] = (tid < ni) ? g_sorted[start + i0 + tid] : 0;
    __syncthreads();
    for (int e = tid; e < 32*ZD; e += 256){
        int r = e >> 7, k = e & 127;
        Us[r][k] = (r < ni) ? g_u[gidx[r]*ZD + k] : 0.f;
    }

    int jj = tid & 31;           // j within tile = lane
    int ig = tid >> 5;           // warp id -> owns rows ig*4..+3
    float sum[4] = {0.f, 0.f, 0.f, 0.f};

    for (int j0 = 0; j0 < cnt; j0 += 32){
        int nj = min(32, cnt - j0);
        __syncthreads();                       // Us visible / Fs+jidx reuse safe
        if (tid < 32) jidx[tid] = (tid < nj) ? g_sorted[start + j0 + tid] : 0;
        __syncthreads();
        for (int e = tid; e < 32*ZD; e += 256){
            int r = e >> 7, k = e & 127;
            Fs[r][k] = (r < nj) ? g_fz[jidx[r]*ZD + k] : 0.f;
        }
        __syncthreads();

        float acc[4] = {0.f, 0.f, 0.f, 0.f};
        #pragma unroll 4
        for (int k = 0; k < ZD; k++){
            float f = Fs[jj][k];
            #pragma unroll
            for (int m = 0; m < 4; m++) acc[m] += Us[ig*4 + m][k]*f;
        }
        #pragma unroll
        for (int m = 0; m < 4; m++){
            float v = (jj < nj) ? softplusf(acc[m]) : 0.f;
            v += __shfl_xor_sync(0xffffffffu, v, 16);
            v += __shfl_xor_sync(0xffffffffu, v, 8);
            v += __shfl_xor_sync(0xffffffffu, v, 4);
            v += __shfl_xor_sync(0xffffffffu, v, 2);
            v += __shfl_xor_sync(0xffffffffu, v, 1);
            sum[m] += v;
        }
    }

    if (jj == 0){
        float inv = 1.f / (float)cnt;
        #pragma unroll
        for (int m = 0; m < 4; m++){
            int rr = ig*4 + m;
            if (rr < ni){
                int gi = gidx[rr];
                float neg = sum[m] * inv;
                out[gi] = logf(g_T[gi] + EPSV) - logf(neg + EPSV);
            }
        }
    }
}

// ---------------- launch ----------------------------------------------------
extern "C" void kernel_launch(void* const* d_in, const int* in_sizes, int n_in,
                              void* d_out, int out_size){
    const float* x  = (const float*)d_in[0];
    const int*   c  = (const int*)  d_in[1];
    const float* z  = (const float*)d_in[2];
    const float* W1 = (const float*)d_in[3];
    const float* b1 = (const float*)d_in[4];
    const float* W2 = (const float*)d_in[5];
    const float* b2 = (const float*)d_in[6];
    const float* Wz = (const float*)d_in[7];
    const float* bz = (const float*)d_in[8];
    const float* Ws = (const float*)d_in[9];
    float* out = (float*)d_out;

    bucket_kernel <<<1, 1024>>>(c);
    fx_kernel     <<<NN/64, 256>>>(x, W1, b1, W2, b2);
    fz_kernel     <<<NN/64, 256>>>(z, Wz, bz);
    u_kernel      <<<NWORK_MAX, 256>>>(Ws);
    neg_kernel    <<<NWORK_MAX, 256>>>(out);
}

// round 6
// speedup vs baseline: 1.1066x; 1.1066x over previous
#include <cuda_runtime.h>

#define NN 8192
#define INDIM 512
#define HID 50
#define ZD 128
#define NCAT 64
#define EPSV 1e-8f
#define NWORK_MAX (NN/32 + NCAT)

// ---------------- scratch (device globals; no allocation allowed) ----------
__device__ float g_fx [NN*ZD];
__device__ float g_fz [NN*ZD];
__device__ float g_us [NN*ZD];   // u in sorted order
__device__ float g_fzs[NN*ZD];   // fz in sorted order
__device__ float g_T  [NN];
__device__ int   g_cnt[NCAT], g_start[NCAT];
__device__ int   g_sorted[NN];
__device__ int   g_work[NWORK_MAX];
__device__ int   g_nwork;

__device__ __forceinline__ float softplusf(float v){
    // stable: max(v,0) + log1p(exp(-|v|)).
    // __expf: ~2 ulp RELATIVE error (safe; log1p preserves relative error).
    // log1pf: accurate — __logf(1+t) would give catastrophic relative error for tiny t.
    return fmaxf(v, 0.f) + log1pf(__expf(-fabsf(v)));
}

// ---------------- fused bucket sort (single block) --------------------------
__global__ void bucket_kernel(const int* __restrict__ c){
    __shared__ int s_cnt[NCAT];
    __shared__ int s_cursor[NCAT];
    __shared__ int s_cat[NN];
    int tid = threadIdx.x;

    if (tid < NCAT) s_cnt[tid] = 0;
    __syncthreads();

    for (int i = tid; i < NN; i += 1024){
        int cc = c[i];
        cc = min(max(cc, 0), NCAT - 1);
        s_cat[i] = cc;
        atomicAdd(&s_cnt[cc], 1);
    }
    __syncthreads();

    if (tid == 0){
        int s = 0, w = 0;
        for (int cc = 0; cc < NCAT; cc++){
            s_cursor[cc] = s;
            g_start[cc]  = s;
            int n = s_cnt[cc];
            g_cnt[cc] = n;
            s += n;
            int nt = (n + 31) >> 5;
            for (int t = 0; t < nt; t++) g_work[w++] = (cc << 16) | t;
        }
        g_nwork = w;
    }
    __syncthreads();

    for (int i = tid; i < NN; i += 1024){
        int p = atomicAdd(&s_cursor[s_cat[i]], 1);
        g_sorted[p] = i;
    }
}

// ---------------- fx = relu(x@W1+b1)@W2+b2  (64 rows / block) --------------
__global__ void fx_kernel(const float* __restrict__ x,  const float* __restrict__ W1,
                          const float* __restrict__ b1, const float* __restrict__ W2,
                          const float* __restrict__ b2){
    __shared__ float sbuf[9664];
    __shared__ float b1s[64];
    __shared__ float b2s[128];
    float (*As)[33]   = (float(*)[33])  sbuf;               // 64x33
    float (*Bs)[64]   = (float(*)[64])  (sbuf + 2112);      // 32x64
    float (*Hs)[51]   = (float(*)[51])  sbuf;               // 64x51 (overlaps, dead)
    float (*W2s)[128] = (float(*)[128]) (sbuf + 3264);      // 50x128

    int tid  = threadIdx.x;
    int row0 = blockIdx.x * 64;
    if (tid < 64)  b1s[tid] = (tid < HID) ? b1[tid] : 0.f;
    if (tid < 128) b2s[tid] = b2[tid];

    int rg = (tid >> 4) * 4;
    int cg = (tid & 15) * 4;
    float acc[4][4] = {};

    for (int k0 = 0; k0 < INDIM; k0 += 32){
        for (int e = tid; e < 64*32; e += 256){
            int r = e >> 5, k = e & 31;
            As[r][k] = x[(row0 + r)*INDIM + k0 + k];
        }
        for (int e = tid; e < 32*64; e += 256){
            int k = e >> 6, j = e & 63;
            Bs[k][j] = (j < HID) ? W1[(k0 + k)*HID + j] : 0.f;
        }
        __syncthreads();
        #pragma unroll
        for (int k = 0; k < 32; k++){
            float a[4], b[4];
            #pragma unroll
            for (int i = 0; i < 4; i++) a[i] = As[rg+i][k];
            #pragma unroll
            for (int j = 0; j < 4; j++) b[j] = Bs[k][cg+j];
            #pragma unroll
            for (int i = 0; i < 4; i++)
                #pragma unroll
                for (int j = 0; j < 4; j++) acc[i][j] += a[i]*b[j];
        }
        __syncthreads();
    }

    #pragma unroll
    for (int i = 0; i < 4; i++)
        #pragma unroll
        for (int j = 0; j < 4; j++){
            int cc = cg + j;
            if (cc < HID) Hs[rg+i][cc] = fmaxf(acc[i][j] + b1s[cc], 0.f);
        }
    for (int e = tid; e < HID*128; e += 256) W2s[e >> 7][e & 127] = W2[e];
    __syncthreads();

    for (int e = tid; e < 64*128; e += 256){
        int r = e >> 7, cc = e & 127;
        float v = b2s[cc];
        #pragma unroll
        for (int k = 0; k < HID; k++) v += Hs[r][k]*W2s[k][cc];
        g_fx[(row0 + r)*ZD + cc] = v;
    }
}

// ---------------- fz = z@Wz+bz  (64 rows / block, k-tiled) -----------------
__global__ void fz_kernel(const float* __restrict__ z, const float* __restrict__ Wz,
                          const float* __restrict__ bz){
    __shared__ float Zs[64][33];
    __shared__ float Wzt[32][128];
    __shared__ float bzs[128];
    int tid  = threadIdx.x;
    int row0 = blockIdx.x * 64;
    if (tid < 128) bzs[tid] = bz[tid];

    int rg = (tid >> 4) * 4;
    int cg = (tid & 15) * 8;
    float acc[4][8] = {};

    for (int kt = 0; kt < ZD; kt += 32){
        for (int e = tid; e < 64*32; e += 256){
            int r = e >> 5, k = e & 31;
            Zs[r][k] = z[(row0 + r)*ZD + kt + k];
        }
        for (int e = tid; e < 32*128; e += 256){
            int k = e >> 7, cc = e & 127;
            Wzt[k][cc] = Wz[(kt + k)*ZD + cc];
        }
        __syncthreads();
        #pragma unroll
        for (int k = 0; k < 32; k++){
            float a[4], b[8];
            #pragma unroll
            for (int i = 0; i < 4; i++) a[i] = Zs[rg+i][k];
            #pragma unroll
            for (int j = 0; j < 8; j++) b[j] = Wzt[k][cg+j];
            #pragma unroll
            for (int i = 0; i < 4; i++)
                #pragma unroll
                for (int j = 0; j < 8; j++) acc[i][j] += a[i]*b[j];
        }
        __syncthreads();
    }
    #pragma unroll
    for (int i = 0; i < 4; i++)
        #pragma unroll
        for (int j = 0; j < 8; j++)
            g_fz[(row0 + rg + i)*ZD + cg + j] = acc[i][j] + bzs[cg+j];
}

// ---------------- u = fx @ Ws[cat]; T = softplus(u . fz) -------------------
// Writes u and fz in SORTED order for neg_kernel. float4/LDS.128 inner loop.
#define FXP 36     // FxsT pitch (floats), %4==0
#define WSP 132    // Wst pitch (floats), %4==0, start banks 4 apart -> LDS.128 conflict-free
__global__ void u_kernel(const float* __restrict__ Ws){
    __shared__ float FxsT[128*FXP];   // [k][r] transposed fx tile
    __shared__ float Wst [32*WSP];    // [k][c]
    __shared__ int   gidx[32];
    int w = blockIdx.x;
    if (w >= g_nwork) return;
    int item  = g_work[w];
    int cat   = item >> 16, tile = item & 0xffff;
    int start = g_start[cat], cnt = g_cnt[cat];
    int i0    = tile * 32;
    int ni    = min(32, cnt - i0);
    int tid   = threadIdx.x;

    if (tid < 32) gidx[tid] = (tid < ni) ? g_sorted[start + i0 + tid] : 0;
    __syncthreads();
    for (int e = tid; e < 32*ZD; e += 256){
        int r = e >> 7, k = e & 127;
        FxsT[k*FXP + r] = (r < ni) ? g_fx[gidx[r]*ZD + k] : 0.f;
    }
    // stage fz into sorted order (global) for neg_kernel
    for (int e = tid; e < 32*ZD; e += 256){
        int r = e >> 7, k = e & 127;
        if (r < ni) g_fzs[(size_t)(start + i0 + r)*ZD + k] = g_fz[(size_t)gidx[r]*ZD + k];
    }

    const float* Wc = Ws + (size_t)cat*ZD*ZD;
    int r0 = (tid >> 5) * 4;     // warp-uniform row group
    int c0 = (tid & 31) * 4;     // lane col group
    float acc[4][4] = {};

    for (int kt = 0; kt < ZD; kt += 32){
        __syncthreads();
        for (int e = tid; e < 32*128; e += 256){
            int k = e >> 7, cc = e & 127;
            Wst[k*WSP + cc] = Wc[(kt + k)*ZD + cc];
        }
        __syncthreads();
        #pragma unroll
        for (int k = 0; k < 32; k++){
            float4 a = *(const float4*)&FxsT[(kt+k)*FXP + r0];   // broadcast
            float4 b = *(const float4*)&Wst [k*WSP + c0];
            acc[0][0] += a.x*b.x; acc[0][1] += a.x*b.y; acc[0][2] += a.x*b.z; acc[0][3] += a.x*b.w;
            acc[1][0] += a.y*b.x; acc[1][1] += a.y*b.y; acc[1][2] += a.y*b.z; acc[1][3] += a.y*b.w;
            acc[2][0] += a.z*b.x; acc[2][1] += a.z*b.y; acc[2][2] += a.z*b.z; acc[2][3] += a.z*b.w;
            acc[3][0] += a.w*b.x; acc[3][1] += a.w*b.y; acc[3][2] += a.w*b.z; acc[3][3] += a.w*b.w;
        }
    }

    int lane = tid & 31;
    #pragma unroll
    for (int i = 0; i < 4; i++){
        int rr = r0 + i;                       // warp-uniform
        float p = 0.f;
        if (rr < ni){
            size_t base = (size_t)(start + i0 + rr)*ZD + c0;
            *(float4*)&g_us[base] = make_float4(acc[i][0], acc[i][1], acc[i][2], acc[i][3]);
            const float4 fzr = *(const float4*)&g_fzs[base];
            p = acc[i][0]*fzr.x + acc[i][1]*fzr.y + acc[i][2]*fzr.z + acc[i][3]*fzr.w;
        }
        p += __shfl_xor_sync(0xffffffffu, p, 16);
        p += __shfl_xor_sync(0xffffffffu, p, 8);
        p += __shfl_xor_sync(0xffffffffu, p, 4);
        p += __shfl_xor_sync(0xffffffffu, p, 2);
        p += __shfl_xor_sync(0xffffffffu, p, 1);
        if (lane == 0 && rr < ni) g_T[gidx[rr]] = softplusf(p);
    }
}

// ---------------- neg_T + final output -------------------------------------
#define TP 132     // tile pitch (floats)
__global__ void neg_kernel(float* __restrict__ out){
    __shared__ float Us[32*TP];
    __shared__ float Fs[32*TP];
    __shared__ int   gidx[32];
    int w = blockIdx.x;
    if (w >= g_nwork) return;
    int item  = g_work[w];
    int cat   = item >> 16, tile = item & 0xffff;
    int start = g_start[cat], cnt = g_cnt[cat];
    int i0    = tile * 32;
    int ni    = min(32, cnt - i0);
    int tid   = threadIdx.x;

    if (tid < 32) gidx[tid] = (tid < ni) ? g_sorted[start + i0 + tid] : 0;
    // load U tile (sorted, contiguous) as float4
    for (int e = tid; e < 32*32; e += 256){
        int r = e >> 5, kq = e & 31;
        float4 v = make_float4(0.f,0.f,0.f,0.f);
        if (r < ni) v = *(const float4*)&g_us[(size_t)(start + i0 + r)*ZD + kq*4];
        *(float4*)&Us[r*TP + kq*4] = v;
    }

    int jj = tid & 31;           // j within tile = lane
    int ig = tid >> 5;           // warp owns rows ig*4..+3
    float sum[4] = {0.f, 0.f, 0.f, 0.f};

    for (int j0 = 0; j0 < cnt; j0 += 32){
        int nj = min(32, cnt - j0);
        __syncthreads();                       // Us visible (1st iter) / Fs reuse safe
        for (int e = tid; e < 32*32; e += 256){
            int r = e >> 5, kq = e & 31;
            float4 v = make_float4(0.f,0.f,0.f,0.f);
            if (r < nj) v = *(const float4*)&g_fzs[(size_t)(start + j0 + r)*ZD + kq*4];
            *(float4*)&Fs[r*TP + kq*4] = v;
        }
        __syncthreads();

        float acc[4] = {0.f, 0.f, 0.f, 0.f};
        #pragma unroll
        for (int k0 = 0; k0 < ZD; k0 += 4){
            float4 f = *(const float4*)&Fs[jj*TP + k0];
            #pragma unroll
            for (int m = 0; m < 4; m++){
                float4 um = *(const float4*)&Us[(ig*4 + m)*TP + k0];   // broadcast
                acc[m] += um.x*f.x + um.y*f.y + um.z*f.z + um.w*f.w;
            }
        }
        #pragma unroll
        for (int m = 0; m < 4; m++){
            float v = (jj < nj) ? softplusf(acc[m]) : 0.f;
            v += __shfl_xor_sync(0xffffffffu, v, 16);
            v += __shfl_xor_sync(0xffffffffu, v, 8);
            v += __shfl_xor_sync(0xffffffffu, v, 4);
            v += __shfl_xor_sync(0xffffffffu, v, 2);
            v += __shfl_xor_sync(0xffffffffu, v, 1);
            sum[m] += v;
        }
    }

    if (jj == 0){
        float inv = 1.f / (float)cnt;
        #pragma unroll
        for (int m = 0; m < 4; m++){
            int rr = ig*4 + m;
            if (rr < ni){
                int gi = gidx[rr];
                out[gi] = logf(g_T[gi] + EPSV) - logf(sum[m]*inv + EPSV);
            }
        }
    }
}

// ---------------- launch ----------------------------------------------------
extern "C" void kernel_launch(void* const* d_in, const int* in_sizes, int n_in,
                              void* d_out, int out_size){
    const float* x  = (const float*)d_in[0];
    const int*   c  = (const int*)  d_in[1];
    const float* z  = (const float*)d_in[2];
    const float* W1 = (const float*)d_in[3];
    const float* b1 = (const float*)d_in[4];
    const float* W2 = (const float*)d_in[5];
    const float* b2 = (const float*)d_in[6];
    const float* Wz = (const float*)d_in[7];
    const float* bz = (const float*)d_in[8];
    const float* Ws = (const float*)d_in[9];
    float* out = (float*)d_out;

    bucket_kernel <<<1, 1024>>>(c);
    fx_kernel     <<<NN/64, 256>>>(x, W1, b1, W2, b2);
    fz_kernel     <<<NN/64, 256>>>(z, Wz, bz);
    u_kernel      <<<NWORK_MAX, 256>>>(Ws);
    neg_kernel    <<<NWORK_MAX, 256>>>(out);
}